// round 14
// baseline (speedup 1.0000x reference)
#include <cuda_runtime.h>
#include <cuda_bf16.h>
#include <math.h>
#include <stdint.h>

// PhasedLSTM B=256,T=1024,H=512 — persistent warp-specialized mma.sync kernel.
// R14 = R12 staging structure + R13 decoupled epilogue, fixing R13's deadlock:
// staging lookahead stays WITHIN the step (never blocks on t+1 flags before
// delivering all 8 chunks of step t), but staging warps (8-15) do not join
// the epilogue — after chunk 7 they roll into step t+1's flag-wait/ldcg/STS
// while mma warps (0-7) run scatter+epilogue+publish. No full-CTA
// __syncthreads in the loop; mma-side ordering via 256-thread named barrier.
// Cross-CTA: 4 independent batch groups, per-producer flags, 4-deep h ring,
// __ldcg h loads. GEMM: split-bf16 3-product (validated 1.148849e-06).

#define Bsz 256
#define Tsz 1024
#define Hsz 512
#define THREADS 512
#define NCHUNK 8
#define NB 4                                  // h ring depth

// named barrier ids (0 = __syncthreads)
#define BAR_FULL0  1
#define BAR_FULL1  2
#define BAR_EMPTY0 3
#define BAR_EMPTY1 4
#define BAR_MMA    5                          // 256-thread mma-warp barrier

// smem byte offsets
#define OFF_W    0                            // w_s[hl][kc][64 n][144B]
#define W_HL_STR 73728
#define W_KC_STR 9216
#define OFF_A    147456                       // a_s[buf][hl][64 row][144B]
#define A_BUF_STR 18432
#define A_HL_STR  9216
#define OFF_PRE  184320                       // preact [64][68] fp32
#define OFF_CST  201728                       // c_state [64][17] fp32
#define OFF_HST  206080                       // h_state [64][17] fp32
#define OFF_WIHB 210432                       // [64 n][4] fp32
#define SMEM_BYTES 211584

__device__ __nv_bfloat16 g_whi[2048 * Hsz];
__device__ __nv_bfloat16 g_wlo[2048 * Hsz];
__device__ __nv_bfloat16 g_hhi[NB][Bsz * Hsz];
__device__ __nv_bfloat16 g_hlo[NB][Bsz * Hsz];
__device__ float g_xT[Tsz * Bsz * 4];
__device__ unsigned g_hflag[4 * 32 * 32];     // [bg][jt], one 128B line each

__global__ void init_kernel(const float* __restrict__ inputs,
                            const float* __restrict__ w_hh) {
    int i = blockIdx.x * blockDim.x + threadIdx.x;
    int nthr = gridDim.x * blockDim.x;
    if (i < 4 * 32 * 32) g_hflag[i] = 0u;
    for (int idx = i; idx < 2048 * Hsz; idx += nthr) {
        float w = w_hh[idx];
        __nv_bfloat16 hi = __float2bfloat16(w);
        g_whi[idx] = hi;
        g_wlo[idx] = __float2bfloat16(w - __bfloat162float(hi));
    }
    for (int idx = i; idx < Bsz * Hsz; idx += nthr) {
        g_hhi[0][idx] = __float2bfloat16(0.0f);
        g_hlo[0][idx] = __float2bfloat16(0.0f);
    }
    for (int idx = i; idx < Bsz * Tsz; idx += nthr) {
        int b = idx >> 10, t = idx & 1023;
        float4 v = *(const float4*)&inputs[(size_t)idx * 4];
        *(float4*)&g_xT[((size_t)t * Bsz + b) * 4] = v;
    }
}

__device__ __forceinline__ uint32_t smem_u32(const void* p) {
    uint32_t a;
    asm("{ .reg .u64 t; cvta.to.shared.u64 t, %1; cvt.u32.u64 %0, t; }"
        : "=r"(a) : "l"(p));
    return a;
}
__device__ __forceinline__ void ldm4(uint32_t* r, uint32_t addr) {
    asm volatile("ldmatrix.sync.aligned.m8n8.x4.shared.b16 {%0,%1,%2,%3}, [%4];"
                 : "=r"(r[0]), "=r"(r[1]), "=r"(r[2]), "=r"(r[3]) : "r"(addr));
}
__device__ __forceinline__ void mma16816(float* d, const uint32_t* a,
                                         const uint32_t* b) {
    asm volatile("mma.sync.aligned.m16n8k16.row.col.f32.bf16.bf16.f32 "
                 "{%0,%1,%2,%3}, {%4,%5,%6,%7}, {%8,%9}, {%0,%1,%2,%3};"
                 : "+f"(d[0]), "+f"(d[1]), "+f"(d[2]), "+f"(d[3])
                 : "r"(a[0]), "r"(a[1]), "r"(a[2]), "r"(a[3]),
                   "r"(b[0]), "r"(b[1]));
}
#define NAMED_SYNC(id, n)   asm volatile("bar.sync %0, %1;" :: "r"(id), "r"(n) : "memory")
#define NAMED_ARRIVE(id, n) asm volatile("bar.arrive %0, %1;" :: "r"(id), "r"(n) : "memory")
#define MEMBAR_CTA()        asm volatile("membar.cta;" ::: "memory")

__device__ __forceinline__ float sig_fast(float x) { return 1.0f / (1.0f + __expf(-x)); }
__device__ __forceinline__ float tanh_fast(float x) {
    float e = __expf(-2.0f * fabsf(x));
    float r = __fdividef(1.0f - e, 1.0f + e);
    return copysignf(r, x);
}

// wait until producers jt0..jt0+cnt-1 of batch group bg have published step t
__device__ __forceinline__ void wait_flags(int bg, int jt0, int cnt, unsigned t) {
    const int l = threadIdx.x & 31;
    if (l < cnt) {
        while (*(volatile unsigned*)&g_hflag[(bg * 32 + jt0 + l) * 32] < t) { }
    }
    __syncwarp();
}

__global__ void __launch_bounds__(THREADS, 1)
plstm_mma(const int*   __restrict__ starts,
          const float* __restrict__ w_ih,
          const float* __restrict__ b_ih,
          const float* __restrict__ b_hh,
          const float* __restrict__ tau,
          const float* __restrict__ phase,
          float* __restrict__ out_final)
{
    extern __shared__ __align__(16) char smem[];
    const uint32_t sbase = smem_u32(smem);
    float* preact = (float*)(smem + OFF_PRE);   // [64][68]
    float* c_st   = (float*)(smem + OFF_CST);   // [64][17]
    float* h_st   = (float*)(smem + OFF_HST);
    float* wihb   = (float*)(smem + OFF_WIHB);  // [64 n][4]

    const int tid    = threadIdx.x;
    const int lane   = tid & 31;
    const int warp   = tid >> 5;
    const bool is_mma = (warp < 8);
    const int warp_m = warp >> 2;
    const int warp_n = warp & 3;
    const int g8     = lane >> 2;
    const int t4     = lane & 3;
    const int jt     = blockIdx.x;              // j-tile 0..31
    const int bg     = blockIdx.y;              // batch group 0..3
    const int j0     = jt * 16;
    const int b0     = bg * 64;
    const int stid   = tid & 255;               // staging lane (warps 8-15)

    const uint32_t aoff = (uint32_t)((warp_m * 32 + (lane & 15)) * 144
                                     + ((lane >> 4) * 16));
    const int n_off = (lane & 7) + ((lane >> 4) << 3);
    const uint32_t boff = (uint32_t)((warp_n * 16 + n_off) * 144
                                     + (((lane >> 3) & 1) * 16));

    // epilogue mapping (mma warps only, 256 threads): batch eb, 4 j each
    const int eb   = tid & 63;
    const int jgrp = (tid >> 6) & 3;            // 0..3

    // ---- one-time staging (all 512 threads) ----
    for (int hl = 0; hl < 2; hl++) {
        const __nv_bfloat16* src = hl ? g_wlo : g_whi;
        char* dstb = smem + OFF_W + hl * W_HL_STR;
        for (int u = tid; u < 64 * 64; u += THREADS) {
            int n = u >> 6, c16 = u & 63;
            int r = (n & 3) * Hsz + j0 + (n >> 2);       // n = j*4+g
            uint4 v = *(const uint4*)&src[(size_t)r * Hsz + c16 * 8];
            int kc = c16 >> 3, cc = c16 & 7;
            *(uint4*)(dstb + kc * W_KC_STR + n * 144 + cc * 16) = v;
        }
    }
    for (int n = tid; n < 64; n += THREADS) {
        int r = (n & 3) * Hsz + j0 + (n >> 2);
        wihb[n * 4 + 0] = w_ih[r * 3 + 0];
        wihb[n * 4 + 1] = w_ih[r * 3 + 1];
        wihb[n * 4 + 2] = w_ih[r * 3 + 2];
        wihb[n * 4 + 3] = b_ih[r] + b_hh[r];
    }
    for (int u = tid; u < 64 * 17; u += THREADS) { c_st[u] = 0.0f; h_st[u] = 0.0f; }

    float tau_r[4], phs_r[4];
    int stb = 0;
    if (is_mma) {
        #pragma unroll
        for (int jj = 0; jj < 4; jj++) {
            tau_r[jj] = tau[j0 + jgrp * 4 + jj];
            phs_r[jj] = phase[j0 + jgrp * 4 + jj];
        }
        stb = starts[b0 + eb];
    }
    __syncthreads();

    if (is_mma) {
        // pre-arm EMPTY barriers (both A buffers writable)
        NAMED_ARRIVE(BAR_EMPTY0, 512);
        NAMED_ARRIVE(BAR_EMPTY1, 512);

        for (int t = 0; t < Tsz; t++) {
            const int wb = (t + 1) & (NB - 1);
            const float4 xv = *(const float4*)&g_xT[((size_t)t * Bsz + b0 + eb) * 4];

            float kk_r[4];
            #pragma unroll
            for (int jj = 0; jj < 4; jj++) {
                const float phi = fabsf(fmodf(xv.z - phs_r[jj], tau_r[jj])) / tau_r[jj];
                const float k_up = phi * 40.0f;
                float kk;
                if (phi < 0.025f)      kk = k_up;
                else if (phi < 0.05f)  kk = 2.0f - k_up;
                else                   kk = 0.001f * phi;
                kk_r[jj] = kk;
            }

            float acc[2][2][4];
            #pragma unroll
            for (int mi = 0; mi < 2; mi++)
                #pragma unroll
                for (int ni = 0; ni < 2; ni++)
                    #pragma unroll
                    for (int e = 0; e < 4; e++) acc[mi][ni][e] = 0.0f;

            for (int kc = 0; kc < NCHUNK; kc++) {
                const int b = kc & 1;
                NAMED_SYNC(BAR_FULL0 + b, 512);   // wait buffer filled
                const uint32_t abase = sbase + OFF_A + b * A_BUF_STR + aoff;
                const uint32_t bbase = sbase + OFF_W + kc * W_KC_STR + boff;
                #pragma unroll
                for (int ks = 0; ks < 4; ks++) {
                    uint32_t ahi[2][4], alo[2][4], bhi[4], blo[4];
                    ldm4(ahi[0], abase + ks * 32);
                    ldm4(ahi[1], abase + ks * 32 + 16 * 144);
                    ldm4(alo[0], abase + A_HL_STR + ks * 32);
                    ldm4(alo[1], abase + A_HL_STR + ks * 32 + 16 * 144);
                    ldm4(bhi, bbase + ks * 32);
                    ldm4(blo, bbase + W_HL_STR + ks * 32);
                    #pragma unroll
                    for (int mi = 0; mi < 2; mi++)
                        #pragma unroll
                        for (int ni = 0; ni < 2; ni++)
                            mma16816(acc[mi][ni], ahi[mi], bhi + 2 * ni);
                    #pragma unroll
                    for (int mi = 0; mi < 2; mi++)
                        #pragma unroll
                        for (int ni = 0; ni < 2; ni++)
                            mma16816(acc[mi][ni], ahi[mi], blo + 2 * ni);
                    #pragma unroll
                    for (int mi = 0; mi < 2; mi++)
                        #pragma unroll
                        for (int ni = 0; ni < 2; ni++)
                            mma16816(acc[mi][ni], alo[mi], bhi + 2 * ni);
                }
                NAMED_ARRIVE(BAR_EMPTY0 + b, 512); // reads done (reg RAW)
            }

            // scatter accumulators to preact tile
            #pragma unroll
            for (int mi = 0; mi < 2; mi++)
                #pragma unroll
                for (int ni = 0; ni < 2; ni++) {
                    const int row = warp_m * 32 + mi * 16 + g8;
                    const int col = warp_n * 16 + ni * 8 + 2 * t4;
                    *(float2*)&preact[row * 68 + col] =
                        make_float2(acc[mi][ni][0], acc[mi][ni][1]);
                    *(float2*)&preact[(row + 8) * 68 + col] =
                        make_float2(acc[mi][ni][2], acc[mi][ni][3]);
                }
            NAMED_SYNC(BAR_MMA, 256);

            // ---- epilogue (mma warps only): batch eb, j = j0+jgrp*4+jj ----
            union { __nv_bfloat16 h[4]; uint2 u; } phi_, plo_;
            float hs_out[4];
            #pragma unroll
            for (int jj = 0; jj < 4; jj++) {
                const int jl = jgrp * 4 + jj;
                const float4 pr = *(const float4*)&preact[eb * 68 + jl * 4];
                const float* prv = (const float*)&pr;
                float pre[4];
                #pragma unroll
                for (int g = 0; g < 4; g++) {
                    const float4 wb4 = *(const float4*)&wihb[(jl * 4 + g) * 4];
                    pre[g] = prv[g] + xv.x * wb4.x + xv.y * wb4.y
                           + xv.w * wb4.z + wb4.w;
                }
                const float iv = sig_fast(pre[0]);
                const float fv = sig_fast(pre[1]);
                const float gv = tanh_fast(pre[2]);
                const float ov = sig_fast(pre[3]);

                const float c0v = c_st[eb * 17 + jl];
                const float h0v = h_st[eb * 17 + jl];
                float cv = fv * c0v + iv * gv;
                float hv = ov * tanh_fast(cv);
                if (t < stb) { cv = c0v; hv = h0v; }

                const float kk = kk_r[jj];
                const float cs = kk * cv + (1.0f - kk) * c0v;
                const float hs = kk * hv + (1.0f - kk) * h0v;
                c_st[eb * 17 + jl] = cs;
                h_st[eb * 17 + jl] = hs;
                hs_out[jj] = hs;

                const __nv_bfloat16 hb = __float2bfloat16(hs);
                phi_.h[jj] = hb;
                plo_.h[jj] = __float2bfloat16(hs - __bfloat162float(hb));
            }
            const size_t gidx = (size_t)(b0 + eb) * Hsz + j0 + jgrp * 4;
            *(uint2*)&g_hhi[wb][gidx] = phi_.u;
            *(uint2*)&g_hlo[wb][gidx] = plo_.u;
            if (t == Tsz - 1)
                *(float4*)&out_final[gidx] = make_float4(hs_out[0], hs_out[1],
                                                         hs_out[2], hs_out[3]);

            // publish: all mma threads' h stores done -> flag
            NAMED_SYNC(BAR_MMA, 256);
            if (tid == 0) {
                __threadfence();
                *(volatile unsigned*)&g_hflag[(bg * 32 + jt) * 32] = (unsigned)(t + 1);
            }
        }
    } else {
        // ---- staging warps: per-step loop, lookahead strictly in-step ----
        // (Deadlock-free: all 8 chunks of step t are delivered before any
        //  wait on step t+1 flags; mma side can thus always complete t and
        //  publish, so flags advance in every CTA of the group.)
        for (int t = 0; t < Tsz; t++) {
            const int rbuf = t & (NB - 1);
            const __nv_bfloat16* __restrict__ hhi = g_hhi[rbuf];
            const __nv_bfloat16* __restrict__ hlo = g_hlo[rbuf];

            wait_flags(bg, 0, 8, (unsigned)t);   // producers of chunks 0,1
            uint4 pv[2][4];
            #pragma unroll
            for (int p = 0; p < 2; p++)
                #pragma unroll
                for (int i = 0; i < 4; i++) {
                    int u = stid + 256 * i;
                    int hl = u >> 9, row = (u >> 3) & 63, c16 = u & 7;
                    const __nv_bfloat16* src = hl ? hlo : hhi;
                    pv[p][i] = __ldcg((const uint4*)&src[(size_t)(b0 + row) * Hsz
                                                         + p * 64 + c16 * 8]);
                }
            for (int kc = 0; kc < NCHUNK; kc++) {
                const int b = kc & 1;
                NAMED_SYNC(BAR_EMPTY0 + b, 512);  // wait buffer consumable
                char* dstb = smem + OFF_A + b * A_BUF_STR;
                #pragma unroll
                for (int i = 0; i < 4; i++) {
                    int u = stid + 256 * i;
                    int hl = u >> 9, row = (u >> 3) & 63, c16 = u & 7;
                    *(uint4*)(dstb + hl * A_HL_STR + row * 144 + c16 * 16) = pv[b][i];
                }
                MEMBAR_CTA();                     // STS visible before arrive
                NAMED_ARRIVE(BAR_FULL0 + b, 512);
                if (kc + 2 < NCHUNK) {
                    wait_flags(bg, 4 * (kc + 2), 4, (unsigned)t);
                    #pragma unroll
                    for (int i = 0; i < 4; i++) {
                        int u = stid + 256 * i;
                        int hl = u >> 9, row = (u >> 3) & 63, c16 = u & 7;
                        const __nv_bfloat16* src = hl ? hlo : hhi;
                        pv[b][i] = __ldcg((const uint4*)&src[(size_t)(b0 + row) * Hsz
                                                             + (kc + 2) * 64 + c16 * 8]);
                    }
                }
            }
        }
    }
}

extern "C" void kernel_launch(void* const* d_in, const int* in_sizes, int n_in,
                              void* d_out, int out_size) {
    (void)in_sizes; (void)n_in; (void)out_size;
    const float* inputs = (const float*)d_in[0];
    const int*   starts = (const int*)  d_in[1];
    const float* w_ih   = (const float*)d_in[2];
    const float* w_hh   = (const float*)d_in[3];
    const float* b_ih   = (const float*)d_in[4];
    const float* b_hh   = (const float*)d_in[5];
    const float* tau    = (const float*)d_in[6];
    const float* phase  = (const float*)d_in[7];
    float* out = (float*)d_out;

    cudaFuncSetAttribute(plstm_mma,
                         cudaFuncAttributeMaxDynamicSharedMemorySize, SMEM_BYTES);

    init_kernel<<<512, 256>>>(inputs, w_hh);

    dim3 grid(32, 4);   // 32 j-tiles x 4 independent batch groups
    plstm_mma<<<grid, THREADS, SMEM_BYTES>>>(starts, w_ih, b_ih, b_hh,
                                             tau, phase, out);
}

// round 16
// speedup vs baseline: 1.3199x; 1.3199x over previous
#include <cuda_runtime.h>
#include <cuda_fp16.h>
#include <math.h>
#include <stdint.h>

// PhasedLSTM B=256,T=1024,H=512 — persistent warp-specialized mma.sync kernel.
// R16 = R15 resubmission (container infra failure; kernel never ran).
// R12 skeleton (best passing) with the GEMM re-split to attack the HMMA
// throughput floor identified in R9-R14 (legacy mma.sync ~512 MAC/cyc/SM on
// sm_100): fp16 2-product  preact = fp16(h) @ (Whi + Wlo), split exact on
// the static weights; only error source is h's fp16 quantization (~2^-12).
// MMA work drops 3->2 products (805M->537M MAC/step). A-staging and h
// write-back traffic halve. Cross-CTA dataflow unchanged: 4 independent
// batch groups, per-producer flags, 4-deep h ring, __ldcg.

#define Bsz 256
#define Tsz 1024
#define Hsz 512
#define THREADS 512
#define NCHUNK 8
#define NB 4                                  // h ring depth

// named barrier ids (0 = __syncthreads)
#define BAR_FULL0  1
#define BAR_FULL1  2
#define BAR_EMPTY0 3
#define BAR_EMPTY1 4

// smem byte offsets
#define OFF_W    0                            // w_s[hl][kc][64 n][144B]
#define W_HL_STR 73728
#define W_KC_STR 9216
#define OFF_A    147456                       // a_s[buf][64 row][144B]
#define A_BUF_STR 9216
#define OFF_PRE  165888                       // preact [64][68] fp32
#define OFF_CST  183296                       // c_state [64][17] fp32
#define OFF_HST  187648                       // h_state [64][17] fp32
#define OFF_WIHB 192000                       // [64 n][4] fp32
#define SMEM_BYTES 193024

__device__ __half g_whi[2048 * Hsz];
__device__ __half g_wlo[2048 * Hsz];
__device__ __half g_h16[NB][Bsz * Hsz];
__device__ float g_xT[Tsz * Bsz * 4];
__device__ unsigned g_hflag[4 * 32 * 32];     // [bg][jt], one 128B line each

__global__ void init_kernel(const float* __restrict__ inputs,
                            const float* __restrict__ w_hh) {
    int i = blockIdx.x * blockDim.x + threadIdx.x;
    int nthr = gridDim.x * blockDim.x;
    if (i < 4 * 32 * 32) g_hflag[i] = 0u;
    for (int idx = i; idx < 2048 * Hsz; idx += nthr) {
        float w = w_hh[idx];
        __half hi = __float2half(w);
        g_whi[idx] = hi;
        g_wlo[idx] = __float2half(w - __half2float(hi));
    }
    for (int idx = i; idx < Bsz * Hsz; idx += nthr)
        g_h16[0][idx] = __float2half(0.0f);
    for (int idx = i; idx < Bsz * Tsz; idx += nthr) {
        int b = idx >> 10, t = idx & 1023;
        float4 v = *(const float4*)&inputs[(size_t)idx * 4];
        *(float4*)&g_xT[((size_t)t * Bsz + b) * 4] = v;
    }
}

__device__ __forceinline__ uint32_t smem_u32(const void* p) {
    uint32_t a;
    asm("{ .reg .u64 t; cvta.to.shared.u64 t, %1; cvt.u32.u64 %0, t; }"
        : "=r"(a) : "l"(p));
    return a;
}
__device__ __forceinline__ void ldm4(uint32_t* r, uint32_t addr) {
    asm volatile("ldmatrix.sync.aligned.m8n8.x4.shared.b16 {%0,%1,%2,%3}, [%4];"
                 : "=r"(r[0]), "=r"(r[1]), "=r"(r[2]), "=r"(r[3]) : "r"(addr));
}
__device__ __forceinline__ void mma16816(float* d, const uint32_t* a,
                                         const uint32_t* b) {
    asm volatile("mma.sync.aligned.m16n8k16.row.col.f32.f16.f16.f32 "
                 "{%0,%1,%2,%3}, {%4,%5,%6,%7}, {%8,%9}, {%0,%1,%2,%3};"
                 : "+f"(d[0]), "+f"(d[1]), "+f"(d[2]), "+f"(d[3])
                 : "r"(a[0]), "r"(a[1]), "r"(a[2]), "r"(a[3]),
                   "r"(b[0]), "r"(b[1]));
}
#define NAMED_SYNC(id, n)   asm volatile("bar.sync %0, %1;" :: "r"(id), "r"(n) : "memory")
#define NAMED_ARRIVE(id, n) asm volatile("bar.arrive %0, %1;" :: "r"(id), "r"(n) : "memory")
#define MEMBAR_CTA()        asm volatile("membar.cta;" ::: "memory")

__device__ __forceinline__ float sig_fast(float x) { return 1.0f / (1.0f + __expf(-x)); }
__device__ __forceinline__ float tanh_fast(float x) {
    float e = __expf(-2.0f * fabsf(x));
    float r = __fdividef(1.0f - e, 1.0f + e);
    return copysignf(r, x);
}

// wait until producers jt0..jt0+cnt-1 of batch group bg have published step t
__device__ __forceinline__ void wait_flags(int bg, int jt0, int cnt, unsigned t) {
    const int l = threadIdx.x & 31;
    if (l < cnt) {
        while (*(volatile unsigned*)&g_hflag[(bg * 32 + jt0 + l) * 32] < t) { }
    }
    __syncwarp();
}

__global__ void __launch_bounds__(THREADS, 1)
plstm_mma(const int*   __restrict__ starts,
          const float* __restrict__ w_ih,
          const float* __restrict__ b_ih,
          const float* __restrict__ b_hh,
          const float* __restrict__ tau,
          const float* __restrict__ phase,
          float* __restrict__ out_final)
{
    extern __shared__ __align__(16) char smem[];
    const uint32_t sbase = smem_u32(smem);
    float* preact = (float*)(smem + OFF_PRE);   // [64][68]
    float* c_st   = (float*)(smem + OFF_CST);   // [64][17]
    float* h_st   = (float*)(smem + OFF_HST);
    float* wihb   = (float*)(smem + OFF_WIHB);  // [64 n][4]

    const int tid    = threadIdx.x;
    const int lane   = tid & 31;
    const int warp   = tid >> 5;
    const bool is_mma = (warp < 8);
    const int warp_m = warp >> 2;
    const int warp_n = warp & 3;
    const int g8     = lane >> 2;
    const int t4     = lane & 3;
    const int jt     = blockIdx.x;              // j-tile 0..31
    const int bg     = blockIdx.y;              // batch group 0..3
    const int j0     = jt * 16;
    const int b0     = bg * 64;
    const int stid   = tid & 255;               // staging lane (warps 8-15)

    const uint32_t aoff = (uint32_t)((warp_m * 32 + (lane & 15)) * 144
                                     + ((lane >> 4) * 16));
    const int n_off = (lane & 7) + ((lane >> 4) << 3);
    const uint32_t boff = (uint32_t)((warp_n * 16 + n_off) * 144
                                     + (((lane >> 3) & 1) * 16));

    const int eb   = tid & 63;
    const int jgrp = tid >> 6;                  // 0..7, 2 j each

    // ---- one-time staging ----
    for (int hl = 0; hl < 2; hl++) {
        const __half* src = hl ? g_wlo : g_whi;
        char* dstb = smem + OFF_W + hl * W_HL_STR;
        for (int u = tid; u < 64 * 64; u += THREADS) {
            int n = u >> 6, c16 = u & 63;
            int r = (n & 3) * Hsz + j0 + (n >> 2);       // n = j*4+g
            uint4 v = *(const uint4*)&src[(size_t)r * Hsz + c16 * 8];
            int kc = c16 >> 3, cc = c16 & 7;
            *(uint4*)(dstb + kc * W_KC_STR + n * 144 + cc * 16) = v;
        }
    }
    for (int n = tid; n < 64; n += THREADS) {
        int r = (n & 3) * Hsz + j0 + (n >> 2);
        wihb[n * 4 + 0] = w_ih[r * 3 + 0];
        wihb[n * 4 + 1] = w_ih[r * 3 + 1];
        wihb[n * 4 + 2] = w_ih[r * 3 + 2];
        wihb[n * 4 + 3] = b_ih[r] + b_hh[r];
    }
    for (int u = tid; u < 64 * 17; u += THREADS) { c_st[u] = 0.0f; h_st[u] = 0.0f; }

    float tau_r[2], phs_r[2];
    #pragma unroll
    for (int jj = 0; jj < 2; jj++) {
        tau_r[jj] = tau[j0 + jgrp * 2 + jj];
        phs_r[jj] = phase[j0 + jgrp * 2 + jj];
    }
    const int stb = starts[b0 + eb];
    __syncthreads();

    // pre-arm EMPTY barriers (buffers start writable)
    if (is_mma) { NAMED_ARRIVE(BAR_EMPTY0, 512); NAMED_ARRIVE(BAR_EMPTY1, 512); }

    for (int t = 0; t < Tsz; t++) {
        const int rbuf = t & (NB - 1);
        const int wbuf = (t + 1) & (NB - 1);
        const __half* __restrict__ h16 = g_h16[rbuf];

        const float4 xv = *(const float4*)&g_xT[((size_t)t * Bsz + b0 + eb) * 4];

        // phased-gate k precompute (off the critical GEMM path)
        float kk_r[2];
        #pragma unroll
        for (int jj = 0; jj < 2; jj++) {
            const float phi = fabsf(fmodf(xv.z - phs_r[jj], tau_r[jj])) / tau_r[jj];
            const float k_up = phi * 40.0f;
            float kk;
            if (phi < 0.025f)      kk = k_up;
            else if (phi < 0.05f)  kk = 2.0f - k_up;
            else                   kk = 0.001f * phi;
            kk_r[jj] = kk;
        }

        if (is_mma) {
            float acc[2][2][4];
            #pragma unroll
            for (int mi = 0; mi < 2; mi++)
                #pragma unroll
                for (int ni = 0; ni < 2; ni++)
                    #pragma unroll
                    for (int e = 0; e < 4; e++) acc[mi][ni][e] = 0.0f;

            for (int kc = 0; kc < NCHUNK; kc++) {
                const int b = kc & 1;
                NAMED_SYNC(BAR_FULL0 + b, 512);   // wait buffer filled
                const uint32_t abase = sbase + OFF_A + b * A_BUF_STR + aoff;
                const uint32_t bbase = sbase + OFF_W + kc * W_KC_STR + boff;
                #pragma unroll
                for (int ks = 0; ks < 4; ks++) {
                    uint32_t a[2][4], bhi[4], blo[4];
                    ldm4(a[0], abase + ks * 32);
                    ldm4(a[1], abase + ks * 32 + 16 * 144);
                    ldm4(bhi, bbase + ks * 32);
                    ldm4(blo, bbase + W_HL_STR + ks * 32);
                    #pragma unroll
                    for (int mi = 0; mi < 2; mi++)
                        #pragma unroll
                        for (int ni = 0; ni < 2; ni++)
                            mma16816(acc[mi][ni], a[mi], bhi + 2 * ni);
                    #pragma unroll
                    for (int mi = 0; mi < 2; mi++)
                        #pragma unroll
                        for (int ni = 0; ni < 2; ni++)
                            mma16816(acc[mi][ni], a[mi], blo + 2 * ni);
                }
                NAMED_ARRIVE(BAR_EMPTY0 + b, 512); // reads done (reg RAW)
            }

            // scatter accumulators to preact tile
            #pragma unroll
            for (int mi = 0; mi < 2; mi++)
                #pragma unroll
                for (int ni = 0; ni < 2; ni++) {
                    const int row = warp_m * 32 + mi * 16 + g8;
                    const int col = warp_n * 16 + ni * 8 + 2 * t4;
                    *(float2*)&preact[row * 68 + col] =
                        make_float2(acc[mi][ni][0], acc[mi][ni][1]);
                    *(float2*)&preact[(row + 8) * 68 + col] =
                        make_float2(acc[mi][ni][2], acc[mi][ni][3]);
                }
        } else {
            // staging: in-step lookahead-2 (deadlock-free), fp16 A chunks
            wait_flags(bg, 0, 8, (unsigned)t);   // producers of chunks 0,1
            uint4 pv[2][2];
            #pragma unroll
            for (int p = 0; p < 2; p++)
                #pragma unroll
                for (int i = 0; i < 2; i++) {
                    int u = stid + 256 * i;
                    int row = u >> 3, c16 = u & 7;
                    pv[p][i] = __ldcg((const uint4*)&h16[(size_t)(b0 + row) * Hsz
                                                         + p * 64 + c16 * 8]);
                }
            for (int kc = 0; kc < NCHUNK; kc++) {
                const int b = kc & 1;
                NAMED_SYNC(BAR_EMPTY0 + b, 512);  // wait buffer consumable
                char* dstb = smem + OFF_A + b * A_BUF_STR;
                #pragma unroll
                for (int i = 0; i < 2; i++) {
                    int u = stid + 256 * i;
                    int row = u >> 3, c16 = u & 7;
                    *(uint4*)(dstb + row * 144 + c16 * 16) = pv[b][i];
                }
                MEMBAR_CTA();                     // STS visible before arrive
                NAMED_ARRIVE(BAR_FULL0 + b, 512);
                if (kc + 2 < NCHUNK) {
                    wait_flags(bg, 4 * (kc + 2), 4, (unsigned)t);
                    #pragma unroll
                    for (int i = 0; i < 2; i++) {
                        int u = stid + 256 * i;
                        int row = u >> 3, c16 = u & 7;
                        pv[b][i] = __ldcg((const uint4*)&h16[(size_t)(b0 + row) * Hsz
                                                             + (kc + 2) * 64 + c16 * 8]);
                    }
                }
            }
        }
        __syncthreads();   // preact ready for all warps

        // ---- epilogue: all 16 warps; thread = batch eb, j = j0+jgrp*2+jj ----
        union { __half h[2]; uint32_t u; } hq_;
        float hs_out[2];
        #pragma unroll
        for (int jj = 0; jj < 2; jj++) {
            const int jl = jgrp * 2 + jj;
            const float4 pr = *(const float4*)&preact[eb * 68 + jl * 4];
            const float* prv = (const float*)&pr;
            float pre[4];
            #pragma unroll
            for (int g = 0; g < 4; g++) {
                const float4 wb4 = *(const float4*)&wihb[(jl * 4 + g) * 4];
                pre[g] = prv[g] + xv.x * wb4.x + xv.y * wb4.y
                       + xv.w * wb4.z + wb4.w;
            }
            const float iv = sig_fast(pre[0]);
            const float fv = sig_fast(pre[1]);
            const float gv = tanh_fast(pre[2]);
            const float ov = sig_fast(pre[3]);

            const float c0v = c_st[eb * 17 + jl];
            const float h0v = h_st[eb * 17 + jl];
            float cv = fv * c0v + iv * gv;
            float hv = ov * tanh_fast(cv);
            if (t < stb) { cv = c0v; hv = h0v; }

            const float kk = kk_r[jj];
            const float cs = kk * cv + (1.0f - kk) * c0v;
            const float hs = kk * hv + (1.0f - kk) * h0v;
            c_st[eb * 17 + jl] = cs;
            h_st[eb * 17 + jl] = hs;
            hs_out[jj] = hs;
            hq_.h[jj] = __float2half(hs);
        }
        const size_t gidx = (size_t)(b0 + eb) * Hsz + j0 + jgrp * 2;
        *(uint32_t*)&g_h16[wbuf][gidx] = hq_.u;
        if (t == Tsz - 1)
            *(float2*)&out_final[gidx] = make_float2(hs_out[0], hs_out[1]);

        // publish: this CTA's h slice for step t+1 is visible
        __syncthreads();
        if (tid == 0) {
            __threadfence();
            *(volatile unsigned*)&g_hflag[(bg * 32 + jt) * 32] = (unsigned)(t + 1);
        }
    }
}

extern "C" void kernel_launch(void* const* d_in, const int* in_sizes, int n_in,
                              void* d_out, int out_size) {
    (void)in_sizes; (void)n_in; (void)out_size;
    const float* inputs = (const float*)d_in[0];
    const int*   starts = (const int*)  d_in[1];
    const float* w_ih   = (const float*)d_in[2];
    const float* w_hh   = (const float*)d_in[3];
    const float* b_ih   = (const float*)d_in[4];
    const float* b_hh   = (const float*)d_in[5];
    const float* tau    = (const float*)d_in[6];
    const float* phase  = (const float*)d_in[7];
    float* out = (float*)d_out;

    cudaFuncSetAttribute(plstm_mma,
                         cudaFuncAttributeMaxDynamicSharedMemorySize, SMEM_BYTES);

    init_kernel<<<512, 256>>>(inputs, w_hh);

    dim3 grid(32, 4);   // 32 j-tiles x 4 independent batch groups
    plstm_mma<<<grid, THREADS, SMEM_BYTES>>>(starts, w_ih, b_ih, b_hh,
                                             tau, phase, out);
}